// round 16
// baseline (speedup 1.0000x reference)
#include <cuda_runtime.h>
#include <cuda_bf16.h>
#include <cuda_fp16.h>
#include <cstdint>

// ===========================================================================
// OccNet folding decoder. conv2 (131072x512x512) as single-term fp16 HMMA
// GEMM (mma.sync m16n8k16) at the legacy-HMMA pipe ceiling (round-10 config,
// untouched). This round: p1 amortizes constants over 16 points/block;
// lin kernels widened to 32 cols/block with 8-way k-split.
// ===========================================================================

// ---------------- device scratch ----------------
__device__ float g_h1[8 * 1024];
__device__ float g_x[8 * 3072];
__device__ float g_fcon[8 * 512];
__device__ __half g_H[131072ull * 512];     // fp16 H (stage-1 output)
__device__ __half g_W[512 * 512];           // W_c2 transposed [N][K], fp16

// ---------------- helpers ----------------
__device__ __forceinline__ uint32_t smem_u32(const void* p) {
    uint32_t a;
    asm("{ .reg .u64 t; cvta.to.shared.u64 t, %1; cvt.u32.u64 %0, t; }"
        : "=r"(a) : "l"(p));
    return a;
}

__device__ __forceinline__ uint32_t h2_bits(__half2 h) {
    return *reinterpret_cast<const uint32_t*>(&h);
}

#define SW128(o) ((o) ^ (((o) >> 3) & 0x70))

#define CP_ASYNC16(dst, src) \
    asm volatile("cp.async.cg.shared.global [%0], [%1], 16;" :: "r"(dst), "l"(src) : "memory")
#define CP_COMMIT() asm volatile("cp.async.commit_group;" ::: "memory")

#define LDSM4(r0, r1, r2, r3, addr) \
    asm volatile("ldmatrix.sync.aligned.m8n8.x4.shared.b16 {%0,%1,%2,%3}, [%4];" \
                 : "=r"(r0), "=r"(r1), "=r"(r2), "=r"(r3) : "r"(addr))

#define MMA_F16(c, a, b0, b1) \
    asm volatile("mma.sync.aligned.m16n8k16.row.col.f32.f16.f16.f32 " \
                 "{%0,%1,%2,%3}, {%4,%5,%6,%7}, {%8,%9}, {%0,%1,%2,%3};" \
                 : "+f"((c)[0]), "+f"((c)[1]), "+f"((c)[2]), "+f"((c)[3]) \
                 : "r"((a)[0]), "r"((a)[1]), "r"((a)[2]), "r"((a)[3]), \
                   "r"(b0), "r"(b1))

// ===========================================================================
// Generic small batched linear, 32 cols/block, 8-way k-split (K=1024, B=8).
// ===========================================================================
__global__ void __launch_bounds__(256)
lin8c_kernel(const float* __restrict__ in, const float* __restrict__ W,
             const float* __restrict__ bias, float* __restrict__ out,
             float* __restrict__ out2, int N, int relu) {
    __shared__ float fs[8192];
    __shared__ float part[2048];
    const int tid = threadIdx.x;
    for (int i = tid; i < 8192; i += 256) fs[i] = in[i];
    __syncthreads();
    const int nl = tid & 31;
    const int kq = tid >> 5;
    const int n = blockIdx.x * 32 + nl;
    float acc[8];
#pragma unroll
    for (int b = 0; b < 8; b++) acc[b] = 0.f;
    const int k0 = kq << 7;
#pragma unroll 4
    for (int k = k0; k < k0 + 128; k++) {
        const float w = W[(size_t)k * N + n];
#pragma unroll
        for (int b = 0; b < 8; b++) acc[b] += fs[(b << 10) + k] * w;
    }
#pragma unroll
    for (int b = 0; b < 8; b++) part[((kq * 8 + b) << 5) | nl] = acc[b];
    __syncthreads();
    if (kq == 0) {
        const float bv = bias[n];
#pragma unroll
        for (int b = 0; b < 8; b++) {
            float v = bv;
#pragma unroll
            for (int s = 0; s < 8; s++) v += part[(((s << 3) + b) << 5) | nl];
            if (relu) v = fmaxf(v, 0.f);
            out[(size_t)b * N + n] = v;
            if (out2) out2[(size_t)b * N + n] = v;
        }
    }
}

// ===========================================================================
// Weight prep: transpose W_c2[K=512][N=512] -> fp16 [N][K].
// ===========================================================================
__global__ void wprep_kernel(const float* __restrict__ W) {
    __shared__ float ts[32][33];
    const int n0 = blockIdx.x * 32, k0 = blockIdx.y * 32;
    const int tx = threadIdx.x, ty = threadIdx.y;
#pragma unroll
    for (int r = 0; r < 32; r += 8)
        ts[ty + r][tx] = W[(size_t)(k0 + ty + r) * 512 + n0 + tx];
    __syncthreads();
#pragma unroll
    for (int r = 0; r < 32; r += 8) {
        const int n = n0 + ty + r, k = k0 + tx;
        g_W[(size_t)n * 512 + k] = __float2half(ts[tx][ty + r]);
    }
}

// ===========================================================================
// P1: stage-1 collapse -> H = relu(fcon + grid/point FMAs), fp16, plus
// fine_out base = b_c3 + center. 16 coarse points per block (constants
// loaded once, amortized x16). Channel octet fixed per thread; 12 float4
// constants hoisted to registers; 64 uint4 stores per thread.
// ===========================================================================
__global__ void __launch_bounds__(256)
p1_kernel(const float* __restrict__ W_c1, const float* __restrict__ b_c3,
          float* __restrict__ fine_out) {
    __shared__ float4 ws4[5 * 128];
    __shared__ float4 fc4[128];
    __shared__ float xs[48];
    const int tid = threadIdx.x;
    const int p0 = blockIdx.x << 4;      // first coarse point (16 per block)
    const int b = p0 >> 10;
    {
        const float4* src = reinterpret_cast<const float4*>(W_c1);
        for (int i = tid; i < 640; i += 256) ws4[i] = src[i];
        const float4* fsrc = reinterpret_cast<const float4*>(g_fcon + b * 512);
        if (tid < 128) fc4[tid] = fsrc[tid];
        if (tid < 48) xs[tid] = g_x[p0 * 3 + tid];
    }
    __syncthreads();

    // fine_out base: 16 pts x 16 rows x 3 comps = 768 values
    for (int i = tid; i < 768; i += 256) {
        const int r = i / 3;             // fine row within block (pt*16+m)
        const int j = i - r * 3;
        fine_out[(size_t)(p0 * 16 + r) * 3 + j] = b_c3[j] + xs[(r >> 4) * 3 + j];
    }

    const float step = 0.1f / 3.0f;
    uint4* H128 = reinterpret_cast<uint4*>(g_H);
    const int cq = tid & 63;             // channel octet — thread-constant
    const int mg = tid >> 6;             // m group (4 m values per thread)

    // hoisted constants (12 x float4 in registers)
    float4 fc[2], w0[2], w1[2], w2[2], w3[2], w4[2];
#pragma unroll
    for (int h = 0; h < 2; h++) {
        const int q = 2 * cq + h;
        fc[h] = fc4[q];
        w0[h] = ws4[q];
        w1[h] = ws4[128 + q];
        w2[h] = ws4[256 + q];
        w3[h] = ws4[384 + q];
        w4[h] = ws4[512 + q];
    }

#pragma unroll 1
    for (int pt = 0; pt < 16; pt++) {
        const float x0 = xs[3 * pt], x1 = xs[3 * pt + 1], x2 = xs[3 * pt + 2];
        // point-term precompute (invariant over m)
        float pv[8];
#pragma unroll
        for (int h = 0; h < 2; h++) {
            pv[4*h+0] = fc[h].x + x0 * w2[h].x + x1 * w3[h].x + x2 * w4[h].x;
            pv[4*h+1] = fc[h].y + x0 * w2[h].y + x1 * w3[h].y + x2 * w4[h].y;
            pv[4*h+2] = fc[h].z + x0 * w2[h].z + x1 * w3[h].z + x2 * w4[h].z;
            pv[4*h+3] = fc[h].w + x0 * w2[h].w + x1 * w3[h].w + x2 * w4[h].w;
        }
        const size_t rowb = ((size_t)(p0 + pt) << 4);
#pragma unroll
        for (int mi = 0; mi < 4; mi++) {
            const int m = mg * 4 + mi;
            const float gx = -0.05f + (float)(m & 3) * step;
            const float gy = -0.05f + (float)(m >> 2) * step;
            float v[8];
#pragma unroll
            for (int h = 0; h < 2; h++) {
                v[4*h+0] = fmaxf(pv[4*h+0] + gx * w0[h].x + gy * w1[h].x, 0.f);
                v[4*h+1] = fmaxf(pv[4*h+1] + gx * w0[h].y + gy * w1[h].y, 0.f);
                v[4*h+2] = fmaxf(pv[4*h+2] + gx * w0[h].z + gy * w1[h].z, 0.f);
                v[4*h+3] = fmaxf(pv[4*h+3] + gx * w0[h].w + gy * w1[h].w, 0.f);
            }
            uint4 o;
            o.x = h2_bits(__floats2half2_rn(v[0], v[1]));
            o.y = h2_bits(__floats2half2_rn(v[2], v[3]));
            o.z = h2_bits(__floats2half2_rn(v[4], v[5]));
            o.w = h2_bits(__floats2half2_rn(v[6], v[7]));
            H128[((rowb + m) << 6) + cq] = o;
        }
    }
}

// ===========================================================================
// conv2 GEMM on fp16 HMMA (round-10 config, mainloop untouched):
// CTA 128(M) x 128(N), 8 warps of 64x32, BK=64, 3-stage cp.async, occ 2.
// Epilogue: bias + relu + conv3 partials -> smem combine -> atomicAdd.
// ===========================================================================
#define STAGE_BYTES 32768            // A 16K | B 16K
#define NSTAGE 3
#define SMEM_MAIN  (NSTAGE * STAGE_BYTES)   // 96 KB
#define G_SMEM     (SMEM_MAIN + 8704)       // + b2s/w3s/psum

__global__ void __launch_bounds__(256, 2)
gemm_kernel(const float* __restrict__ b_c2, const float* __restrict__ W_c3,
            float* __restrict__ fine_out) {
    extern __shared__ __align__(1024) char sm[];
    const uint32_t sbase = smem_u32(sm);
    const int tid = threadIdx.x;
    const int nb = blockIdx.x;           // N block 0..3
    const int n0 = nb << 7;
    const int row0 = blockIdx.y << 7;    // M block * 128

    float* b2s = (float*)(sm + SMEM_MAIN);          // 128 f
    float* w3s = (float*)(sm + SMEM_MAIN + 512);    // 384 f
    float* psum = (float*)(sm + SMEM_MAIN + 2048);  // [4][128][3] f

    if (tid < 128) b2s[tid] = b_c2[n0 + tid];
    for (int i = tid; i < 384; i += 256) w3s[i] = W_c3[n0 * 3 + i];

    const int lane = tid & 31, warp = tid >> 5;
    const int wm = warp >> 2, wn = warp & 3;        // 2 x 4 warp grid

    // stage loader: 8 cp.async(16B) per thread
    auto load_stage = [&](int s, int c) {
        const uint32_t buf = sbase + s * STAGE_BYTES;
        const int k0 = c << 6;
#pragma unroll
        for (int t = 0; t < 4; t++) {               // A
            const int i = (t << 8) + tid;           // 0..1023
            const int rr = i >> 3, q = i & 7;
            const __half* src = g_H + (((size_t)(row0 + rr)) << 9) + k0 + (q << 3);
            CP_ASYNC16(buf + SW128((rr << 7) + (q << 4)), src);
        }
#pragma unroll
        for (int t = 0; t < 4; t++) {               // B
            const int i = (t << 8) + tid;
            const int nn = i >> 3, q = i & 7;
            const __half* src = g_W + (((size_t)(n0 + nn)) << 9) + k0 + (q << 3);
            CP_ASYNC16(buf + 16384 + SW128((nn << 7) + (q << 4)), src);
        }
        CP_COMMIT();
    };

    float acc[4][4][4];
#pragma unroll
    for (int i = 0; i < 4; i++)
#pragma unroll
        for (int j = 0; j < 4; j++)
#pragma unroll
            for (int c = 0; c < 4; c++) acc[i][j][c] = 0.f;

    // per-lane ldmatrix base offsets (row*128, swizzle xor from row&7)
    const uint32_t lxor = (uint32_t)(lane & 7) << 4;
    uint32_t arow[4], brow[2];
#pragma unroll
    for (int i = 0; i < 4; i++) arow[i] = (uint32_t)((wm * 64 + i * 16 + (lane & 15)) << 7);
#pragma unroll
    for (int jj = 0; jj < 2; jj++) brow[jj] = (uint32_t)((wn * 32 + jj * 16 + (lane & 15)) << 7);

    load_stage(0, 0);
    load_stage(1, 1);

#pragma unroll 1
    for (int c = 0; c < 8; ++c) {
        if (c < 7) asm volatile("cp.async.wait_group 1;" ::: "memory");
        else       asm volatile("cp.async.wait_group 0;" ::: "memory");
        __syncthreads();   // also orders prior-iter reads before next write
        if (c + 2 < 8) load_stage((c + 2) % NSTAGE, c + 2);

        const uint32_t sa = sbase + (uint32_t)(c % NSTAGE) * STAGE_BYTES;
        const uint32_t sb = sa + 16384;
#pragma unroll
        for (int t = 0; t < 4; ++t) {
            const uint32_t koff = ((uint32_t)t << 5) + (((uint32_t)lane >> 4) << 4);
            const uint32_t ks = koff ^ lxor;
            uint32_t ah[4][4], bh[2][4];
#pragma unroll
            for (int i = 0; i < 4; i++)
                LDSM4(ah[i][0], ah[i][1], ah[i][2], ah[i][3], sa + arow[i] + ks);
#pragma unroll
            for (int jj = 0; jj < 2; jj++)
                LDSM4(bh[jj][0], bh[jj][1], bh[jj][2], bh[jj][3], sb + brow[jj] + ks);
            // x4 B regs: frag n(0-7) -> {r0, r2}; n(8-15) -> {r1, r3}
#pragma unroll
            for (int i = 0; i < 4; i++)
#pragma unroll
                for (int jj = 0; jj < 2; jj++) {
                    MMA_F16(acc[i][2 * jj],     ah[i], bh[jj][0], bh[jj][2]);
                    MMA_F16(acc[i][2 * jj + 1], ah[i], bh[jj][1], bh[jj][3]);
                }
        }
    }
    __syncthreads();

    // ---- epilogue: bias + relu + conv3 partials over 128 cols -------------
    // acc frag (i,j): rows wm*64+i*16 + lane/4 + {0,8};
    //                 cols wn*32 + j*8 + (lane%4)*2 + {0,1}
#pragma unroll
    for (int i = 0; i < 4; i++) {
        float s0x = 0.f, s0y = 0.f, s0z = 0.f;
        float s1x = 0.f, s1y = 0.f, s1z = 0.f;
#pragma unroll
        for (int j = 0; j < 4; j++) {
            const int colb = wn * 32 + j * 8 + (lane & 3) * 2;
#pragma unroll
            for (int cc = 0; cc < 4; cc++) {
                const int col = colb + (cc & 1);
                const float v = fmaxf(acc[i][j][cc] + b2s[col], 0.f);
                const float w0 = w3s[col * 3 + 0];
                const float w1 = w3s[col * 3 + 1];
                const float w2 = w3s[col * 3 + 2];
                if (cc < 2) { s0x += v * w0; s0y += v * w1; s0z += v * w2; }
                else        { s1x += v * w0; s1y += v * w1; s1z += v * w2; }
            }
        }
#pragma unroll
        for (int d = 1; d < 4; d <<= 1) {
            s0x += __shfl_xor_sync(0xffffffffu, s0x, d);
            s0y += __shfl_xor_sync(0xffffffffu, s0y, d);
            s0z += __shfl_xor_sync(0xffffffffu, s0z, d);
            s1x += __shfl_xor_sync(0xffffffffu, s1x, d);
            s1y += __shfl_xor_sync(0xffffffffu, s1y, d);
            s1z += __shfl_xor_sync(0xffffffffu, s1z, d);
        }
        if ((lane & 3) == 0) {
            const int r = wm * 64 + i * 16 + (lane >> 2);
            psum[(wn * 128 + r) * 3 + 0] = s0x;
            psum[(wn * 128 + r) * 3 + 1] = s0y;
            psum[(wn * 128 + r) * 3 + 2] = s0z;
            psum[(wn * 128 + r + 8) * 3 + 0] = s1x;
            psum[(wn * 128 + r + 8) * 3 + 1] = s1y;
            psum[(wn * 128 + r + 8) * 3 + 2] = s1z;
        }
    }
    __syncthreads();
    if (tid < 128) {
#pragma unroll
        for (int j = 0; j < 3; j++) {
            const float s = psum[(0 * 128 + tid) * 3 + j] + psum[(1 * 128 + tid) * 3 + j]
                          + psum[(2 * 128 + tid) * 3 + j] + psum[(3 * 128 + tid) * 3 + j];
            atomicAdd(&fine_out[(size_t)(row0 + tid) * 3 + j], s);
        }
    }
}

// ===========================================================================
extern "C" void kernel_launch(void* const* d_in, const int* in_sizes, int n_in,
                              void* d_out, int out_size) {
    const float* fea  = (const float*)d_in[0];
    const float* W_l1 = (const float*)d_in[1];
    const float* b_l1 = (const float*)d_in[2];
    const float* W_l2 = (const float*)d_in[3];
    const float* b_l2 = (const float*)d_in[4];
    const float* W_c1 = (const float*)d_in[5];
    const float* b_c1 = (const float*)d_in[6];
    const float* W_c2 = (const float*)d_in[7];
    const float* b_c2 = (const float*)d_in[8];
    const float* W_c3 = (const float*)d_in[9];
    const float* b_c3 = (const float*)d_in[10];

    float* out = (float*)d_out;
    float* xout = nullptr;
    float* fineout = out;
    if (out_size >= 24576 + 393216) {   // x (8*1024*3) then fine (8*16384*3)
        xout = out;
        fineout = out + 24576;
    }

    float *h1p, *xp, *fcp;
    cudaGetSymbolAddress((void**)&h1p, g_h1);
    cudaGetSymbolAddress((void**)&xp, g_x);
    cudaGetSymbolAddress((void**)&fcp, g_fcon);
    cudaFuncSetAttribute(gemm_kernel,
                         cudaFuncAttributeMaxDynamicSharedMemorySize, G_SMEM);

    // independent weight transpose first
    wprep_kernel<<<dim3(16, 16), dim3(32, 8)>>>(W_c2);

    // coarse branch: lin1 + fcon (parallel-width 48+16), then lin2 (96)
    lin8c_kernel<<<32, 256>>>(fea, W_l1, b_l1, h1p, nullptr, 1024, 1);
    lin8c_kernel<<<16, 256>>>(fea, W_c1 + 5 * 512, b_c1, fcp, nullptr, 512, 0);
    lin8c_kernel<<<96, 256>>>(h1p, W_l2, b_l2, xp, xout, 3072, 0);

    // H production (fp16) + fine_out base; 16 points per block
    p1_kernel<<<512, 256>>>(W_c1, b_c3, fineout);

    // conv2 fp16 HMMA GEMM; epilogue atomically adds conv3 partials
    gemm_kernel<<<dim3(4, 1024), 256, G_SMEM>>>(b_c2, W_c3, fineout);
}

// round 17
// speedup vs baseline: 1.0906x; 1.0906x over previous
#include <cuda_runtime.h>
#include <cuda_bf16.h>
#include <cuda_fp16.h>
#include <cstdint>

// ===========================================================================
// OccNet folding decoder. conv2 (131072x512x512) as single-term fp16 HMMA
// GEMM (mma.sync m16n8k16) at the legacy-HMMA pipe ceiling (round-10 config,
// untouched). This round: recombination of measured winners — round-15 lin
// kernels (64 cols/block) + round-16 p1 (16 points/block) + fused epilogue.
// ===========================================================================

// ---------------- device scratch ----------------
__device__ float g_h1[8 * 1024];
__device__ float g_x[8 * 3072];
__device__ float g_fcon[8 * 512];
__device__ __half g_H[131072ull * 512];     // fp16 H (stage-1 output)
__device__ __half g_W[512 * 512];           // W_c2 transposed [N][K], fp16

// ---------------- helpers ----------------
__device__ __forceinline__ uint32_t smem_u32(const void* p) {
    uint32_t a;
    asm("{ .reg .u64 t; cvta.to.shared.u64 t, %1; cvt.u32.u64 %0, t; }"
        : "=r"(a) : "l"(p));
    return a;
}

__device__ __forceinline__ uint32_t h2_bits(__half2 h) {
    return *reinterpret_cast<const uint32_t*>(&h);
}

#define SW128(o) ((o) ^ (((o) >> 3) & 0x70))

#define CP_ASYNC16(dst, src) \
    asm volatile("cp.async.cg.shared.global [%0], [%1], 16;" :: "r"(dst), "l"(src) : "memory")
#define CP_COMMIT() asm volatile("cp.async.commit_group;" ::: "memory")

#define LDSM4(r0, r1, r2, r3, addr) \
    asm volatile("ldmatrix.sync.aligned.m8n8.x4.shared.b16 {%0,%1,%2,%3}, [%4];" \
                 : "=r"(r0), "=r"(r1), "=r"(r2), "=r"(r3) : "r"(addr))

#define MMA_F16(c, a, b0, b1) \
    asm volatile("mma.sync.aligned.m16n8k16.row.col.f32.f16.f16.f32 " \
                 "{%0,%1,%2,%3}, {%4,%5,%6,%7}, {%8,%9}, {%0,%1,%2,%3};" \
                 : "+f"((c)[0]), "+f"((c)[1]), "+f"((c)[2]), "+f"((c)[3]) \
                 : "r"((a)[0]), "r"((a)[1]), "r"((a)[2]), "r"((a)[3]), \
                   "r"(b0), "r"(b1))

// ===========================================================================
// Fused small linears over fea (K=1024, B=8), 64 cols/block, 4-way k-split:
//   blocks 0..15 : h1[b,n]   = relu(fea @ W_l1 + b_l1), N=1024
//   blocks 16..23: fcon[b,n] = fea @ W_c1[5:,:] + b_c1,  N=512
// ===========================================================================
__global__ void __launch_bounds__(256)
linA_kernel(const float* __restrict__ fea,
            const float* __restrict__ W_l1, const float* __restrict__ b_l1,
            const float* __restrict__ W_c1c, const float* __restrict__ b_c1,
            float* __restrict__ h1, float* __restrict__ fcon) {
    __shared__ float fs[8192];
    __shared__ float part[2048];
    const int tid = threadIdx.x;
    for (int i = tid; i < 8192; i += 256) fs[i] = fea[i];
    __syncthreads();
    const int nl = tid & 63;
    const int kq = tid >> 6;
    const bool is1 = blockIdx.x < 16;
    const int N = is1 ? 1024 : 512;
    const int n = (is1 ? blockIdx.x : blockIdx.x - 16) * 64 + nl;
    const float* W = is1 ? W_l1 : W_c1c;
    float acc[8];
#pragma unroll
    for (int b = 0; b < 8; b++) acc[b] = 0.f;
    const int k0 = kq << 8;
#pragma unroll 4
    for (int k = k0; k < k0 + 256; k++) {
        const float w = W[(size_t)k * N + n];
#pragma unroll
        for (int b = 0; b < 8; b++) acc[b] += fs[(b << 10) + k] * w;
    }
#pragma unroll
    for (int b = 0; b < 8; b++) part[((kq * 8 + b) << 6) | nl] = acc[b];
    __syncthreads();
    if (kq == 0) {
        const float bv = is1 ? b_l1[n] : b_c1[n];
        float* out = is1 ? h1 : fcon;
#pragma unroll
        for (int b = 0; b < 8; b++) {
            float v = part[(b << 6) | nl] + part[((8 + b) << 6) | nl]
                    + part[((16 + b) << 6) | nl] + part[((24 + b) << 6) | nl] + bv;
            if (is1) v = fmaxf(v, 0.f);
            out[(size_t)b * N + n] = v;
        }
    }
}

// ===========================================================================
// lin2: x[b,n] = h1[b,:] @ W_l2 + b_l2, N=3072, K=1024 (writes x + xout copy)
// ===========================================================================
__global__ void __launch_bounds__(256)
lin2_kernel(const float* __restrict__ in, const float* __restrict__ W,
            const float* __restrict__ bias, float* __restrict__ out,
            float* __restrict__ out2) {
    __shared__ float fs[8192];
    __shared__ float part[2048];
    const int tid = threadIdx.x;
    for (int i = tid; i < 8192; i += 256) fs[i] = in[i];
    __syncthreads();
    const int nl = tid & 63;
    const int kq = tid >> 6;
    const int n = blockIdx.x * 64 + nl;
    float acc[8];
#pragma unroll
    for (int b = 0; b < 8; b++) acc[b] = 0.f;
    const int k0 = kq << 8;
#pragma unroll 4
    for (int k = k0; k < k0 + 256; k++) {
        const float w = W[(size_t)k * 3072 + n];
#pragma unroll
        for (int b = 0; b < 8; b++) acc[b] += fs[(b << 10) + k] * w;
    }
#pragma unroll
    for (int b = 0; b < 8; b++) part[((kq * 8 + b) << 6) | nl] = acc[b];
    __syncthreads();
    if (kq == 0) {
        const float bv = bias[n];
#pragma unroll
        for (int b = 0; b < 8; b++) {
            float v = part[(b << 6) | nl] + part[((8 + b) << 6) | nl]
                    + part[((16 + b) << 6) | nl] + part[((24 + b) << 6) | nl] + bv;
            out[(size_t)b * 3072 + n] = v;
            if (out2) out2[(size_t)b * 3072 + n] = v;
        }
    }
}

// ===========================================================================
// Weight prep: transpose W_c2[K=512][N=512] -> fp16 [N][K].
// ===========================================================================
__global__ void wprep_kernel(const float* __restrict__ W) {
    __shared__ float ts[32][33];
    const int n0 = blockIdx.x * 32, k0 = blockIdx.y * 32;
    const int tx = threadIdx.x, ty = threadIdx.y;
#pragma unroll
    for (int r = 0; r < 32; r += 8)
        ts[ty + r][tx] = W[(size_t)(k0 + ty + r) * 512 + n0 + tx];
    __syncthreads();
#pragma unroll
    for (int r = 0; r < 32; r += 8) {
        const int n = n0 + ty + r, k = k0 + tx;
        g_W[(size_t)n * 512 + k] = __float2half(ts[tx][ty + r]);
    }
}

// ===========================================================================
// P1: stage-1 collapse -> H = relu(fcon + grid/point FMAs), fp16, plus
// fine_out base = b_c3 + center. 16 coarse points per block (constants
// loaded once, amortized x16). Channel octet fixed per thread; 12 float4
// constants hoisted to registers; 64 uint4 stores per thread.
// ===========================================================================
__global__ void __launch_bounds__(256)
p1_kernel(const float* __restrict__ W_c1, const float* __restrict__ b_c3,
          float* __restrict__ fine_out) {
    __shared__ float4 ws4[5 * 128];
    __shared__ float4 fc4[128];
    __shared__ float xs[48];
    const int tid = threadIdx.x;
    const int p0 = blockIdx.x << 4;      // first coarse point (16 per block)
    const int b = p0 >> 10;
    {
        const float4* src = reinterpret_cast<const float4*>(W_c1);
        for (int i = tid; i < 640; i += 256) ws4[i] = src[i];
        const float4* fsrc = reinterpret_cast<const float4*>(g_fcon + b * 512);
        if (tid < 128) fc4[tid] = fsrc[tid];
        if (tid < 48) xs[tid] = g_x[p0 * 3 + tid];
    }
    __syncthreads();

    // fine_out base: 16 pts x 16 rows x 3 comps = 768 values
    for (int i = tid; i < 768; i += 256) {
        const int r = i / 3;             // fine row within block (pt*16+m)
        const int j = i - r * 3;
        fine_out[(size_t)(p0 * 16 + r) * 3 + j] = b_c3[j] + xs[(r >> 4) * 3 + j];
    }

    const float step = 0.1f / 3.0f;
    uint4* H128 = reinterpret_cast<uint4*>(g_H);
    const int cq = tid & 63;             // channel octet — thread-constant
    const int mg = tid >> 6;             // m group (4 m values per thread)

    // hoisted constants (12 x float4 in registers)
    float4 fc[2], w0[2], w1[2], w2[2], w3[2], w4[2];
#pragma unroll
    for (int h = 0; h < 2; h++) {
        const int q = 2 * cq + h;
        fc[h] = fc4[q];
        w0[h] = ws4[q];
        w1[h] = ws4[128 + q];
        w2[h] = ws4[256 + q];
        w3[h] = ws4[384 + q];
        w4[h] = ws4[512 + q];
    }

#pragma unroll 1
    for (int pt = 0; pt < 16; pt++) {
        const float x0 = xs[3 * pt], x1 = xs[3 * pt + 1], x2 = xs[3 * pt + 2];
        // point-term precompute (invariant over m)
        float pv[8];
#pragma unroll
        for (int h = 0; h < 2; h++) {
            pv[4*h+0] = fc[h].x + x0 * w2[h].x + x1 * w3[h].x + x2 * w4[h].x;
            pv[4*h+1] = fc[h].y + x0 * w2[h].y + x1 * w3[h].y + x2 * w4[h].y;
            pv[4*h+2] = fc[h].z + x0 * w2[h].z + x1 * w3[h].z + x2 * w4[h].z;
            pv[4*h+3] = fc[h].w + x0 * w2[h].w + x1 * w3[h].w + x2 * w4[h].w;
        }
        const size_t rowb = ((size_t)(p0 + pt) << 4);
#pragma unroll
        for (int mi = 0; mi < 4; mi++) {
            const int m = mg * 4 + mi;
            const float gx = -0.05f + (float)(m & 3) * step;
            const float gy = -0.05f + (float)(m >> 2) * step;
            float v[8];
#pragma unroll
            for (int h = 0; h < 2; h++) {
                v[4*h+0] = fmaxf(pv[4*h+0] + gx * w0[h].x + gy * w1[h].x, 0.f);
                v[4*h+1] = fmaxf(pv[4*h+1] + gx * w0[h].y + gy * w1[h].y, 0.f);
                v[4*h+2] = fmaxf(pv[4*h+2] + gx * w0[h].z + gy * w1[h].z, 0.f);
                v[4*h+3] = fmaxf(pv[4*h+3] + gx * w0[h].w + gy * w1[h].w, 0.f);
            }
            uint4 o;
            o.x = h2_bits(__floats2half2_rn(v[0], v[1]));
            o.y = h2_bits(__floats2half2_rn(v[2], v[3]));
            o.z = h2_bits(__floats2half2_rn(v[4], v[5]));
            o.w = h2_bits(__floats2half2_rn(v[6], v[7]));
            H128[((rowb + m) << 6) + cq] = o;
        }
    }
}

// ===========================================================================
// conv2 GEMM on fp16 HMMA (round-10 config, mainloop untouched):
// CTA 128(M) x 128(N), 8 warps of 64x32, BK=64, 3-stage cp.async, occ 2.
// Epilogue: bias + relu + conv3 partials -> smem combine -> atomicAdd.
// ===========================================================================
#define STAGE_BYTES 32768            // A 16K | B 16K
#define NSTAGE 3
#define SMEM_MAIN  (NSTAGE * STAGE_BYTES)   // 96 KB
#define G_SMEM     (SMEM_MAIN + 8704)       // + b2s/w3s/psum

__global__ void __launch_bounds__(256, 2)
gemm_kernel(const float* __restrict__ b_c2, const float* __restrict__ W_c3,
            float* __restrict__ fine_out) {
    extern __shared__ __align__(1024) char sm[];
    const uint32_t sbase = smem_u32(sm);
    const int tid = threadIdx.x;
    const int nb = blockIdx.x;           // N block 0..3
    const int n0 = nb << 7;
    const int row0 = blockIdx.y << 7;    // M block * 128

    float* b2s = (float*)(sm + SMEM_MAIN);          // 128 f
    float* w3s = (float*)(sm + SMEM_MAIN + 512);    // 384 f
    float* psum = (float*)(sm + SMEM_MAIN + 2048);  // [4][128][3] f

    if (tid < 128) b2s[tid] = b_c2[n0 + tid];
    for (int i = tid; i < 384; i += 256) w3s[i] = W_c3[n0 * 3 + i];

    const int lane = tid & 31, warp = tid >> 5;
    const int wm = warp >> 2, wn = warp & 3;        // 2 x 4 warp grid

    // stage loader: 8 cp.async(16B) per thread
    auto load_stage = [&](int s, int c) {
        const uint32_t buf = sbase + s * STAGE_BYTES;
        const int k0 = c << 6;
#pragma unroll
        for (int t = 0; t < 4; t++) {               // A
            const int i = (t << 8) + tid;           // 0..1023
            const int rr = i >> 3, q = i & 7;
            const __half* src = g_H + (((size_t)(row0 + rr)) << 9) + k0 + (q << 3);
            CP_ASYNC16(buf + SW128((rr << 7) + (q << 4)), src);
        }
#pragma unroll
        for (int t = 0; t < 4; t++) {               // B
            const int i = (t << 8) + tid;
            const int nn = i >> 3, q = i & 7;
            const __half* src = g_W + (((size_t)(n0 + nn)) << 9) + k0 + (q << 3);
            CP_ASYNC16(buf + 16384 + SW128((nn << 7) + (q << 4)), src);
        }
        CP_COMMIT();
    };

    float acc[4][4][4];
#pragma unroll
    for (int i = 0; i < 4; i++)
#pragma unroll
        for (int j = 0; j < 4; j++)
#pragma unroll
            for (int c = 0; c < 4; c++) acc[i][j][c] = 0.f;

    // per-lane ldmatrix base offsets (row*128, swizzle xor from row&7)
    const uint32_t lxor = (uint32_t)(lane & 7) << 4;
    uint32_t arow[4], brow[2];
#pragma unroll
    for (int i = 0; i < 4; i++) arow[i] = (uint32_t)((wm * 64 + i * 16 + (lane & 15)) << 7);
#pragma unroll
    for (int jj = 0; jj < 2; jj++) brow[jj] = (uint32_t)((wn * 32 + jj * 16 + (lane & 15)) << 7);

    load_stage(0, 0);
    load_stage(1, 1);

#pragma unroll 1
    for (int c = 0; c < 8; ++c) {
        if (c < 7) asm volatile("cp.async.wait_group 1;" ::: "memory");
        else       asm volatile("cp.async.wait_group 0;" ::: "memory");
        __syncthreads();   // also orders prior-iter reads before next write
        if (c + 2 < 8) load_stage((c + 2) % NSTAGE, c + 2);

        const uint32_t sa = sbase + (uint32_t)(c % NSTAGE) * STAGE_BYTES;
        const uint32_t sb = sa + 16384;
#pragma unroll
        for (int t = 0; t < 4; ++t) {
            const uint32_t koff = ((uint32_t)t << 5) + (((uint32_t)lane >> 4) << 4);
            const uint32_t ks = koff ^ lxor;
            uint32_t ah[4][4], bh[2][4];
#pragma unroll
            for (int i = 0; i < 4; i++)
                LDSM4(ah[i][0], ah[i][1], ah[i][2], ah[i][3], sa + arow[i] + ks);
#pragma unroll
            for (int jj = 0; jj < 2; jj++)
                LDSM4(bh[jj][0], bh[jj][1], bh[jj][2], bh[jj][3], sb + brow[jj] + ks);
            // x4 B regs: frag n(0-7) -> {r0, r2}; n(8-15) -> {r1, r3}
#pragma unroll
            for (int i = 0; i < 4; i++)
#pragma unroll
                for (int jj = 0; jj < 2; jj++) {
                    MMA_F16(acc[i][2 * jj],     ah[i], bh[jj][0], bh[jj][2]);
                    MMA_F16(acc[i][2 * jj + 1], ah[i], bh[jj][1], bh[jj][3]);
                }
        }
    }
    __syncthreads();

    // ---- epilogue: bias + relu + conv3 partials over 128 cols -------------
    // acc frag (i,j): rows wm*64+i*16 + lane/4 + {0,8};
    //                 cols wn*32 + j*8 + (lane%4)*2 + {0,1}
#pragma unroll
    for (int i = 0; i < 4; i++) {
        float s0x = 0.f, s0y = 0.f, s0z = 0.f;
        float s1x = 0.f, s1y = 0.f, s1z = 0.f;
#pragma unroll
        for (int j = 0; j < 4; j++) {
            const int colb = wn * 32 + j * 8 + (lane & 3) * 2;
#pragma unroll
            for (int cc = 0; cc < 4; cc++) {
                const int col = colb + (cc & 1);
                const float v = fmaxf(acc[i][j][cc] + b2s[col], 0.f);
                const float w0 = w3s[col * 3 + 0];
                const float w1 = w3s[col * 3 + 1];
                const float w2 = w3s[col * 3 + 2];
                if (cc < 2) { s0x += v * w0; s0y += v * w1; s0z += v * w2; }
                else        { s1x += v * w0; s1y += v * w1; s1z += v * w2; }
            }
        }
#pragma unroll
        for (int d = 1; d < 4; d <<= 1) {
            s0x += __shfl_xor_sync(0xffffffffu, s0x, d);
            s0y += __shfl_xor_sync(0xffffffffu, s0y, d);
            s0z += __shfl_xor_sync(0xffffffffu, s0z, d);
            s1x += __shfl_xor_sync(0xffffffffu, s1x, d);
            s1y += __shfl_xor_sync(0xffffffffu, s1y, d);
            s1z += __shfl_xor_sync(0xffffffffu, s1z, d);
        }
        if ((lane & 3) == 0) {
            const int r = wm * 64 + i * 16 + (lane >> 2);
            psum[(wn * 128 + r) * 3 + 0] = s0x;
            psum[(wn * 128 + r) * 3 + 1] = s0y;
            psum[(wn * 128 + r) * 3 + 2] = s0z;
            psum[(wn * 128 + r + 8) * 3 + 0] = s1x;
            psum[(wn * 128 + r + 8) * 3 + 1] = s1y;
            psum[(wn * 128 + r + 8) * 3 + 2] = s1z;
        }
    }
    __syncthreads();
    if (tid < 128) {
#pragma unroll
        for (int j = 0; j < 3; j++) {
            const float s = psum[(0 * 128 + tid) * 3 + j] + psum[(1 * 128 + tid) * 3 + j]
                          + psum[(2 * 128 + tid) * 3 + j] + psum[(3 * 128 + tid) * 3 + j];
            atomicAdd(&fine_out[(size_t)(row0 + tid) * 3 + j], s);
        }
    }
}

// ===========================================================================
extern "C" void kernel_launch(void* const* d_in, const int* in_sizes, int n_in,
                              void* d_out, int out_size) {
    const float* fea  = (const float*)d_in[0];
    const float* W_l1 = (const float*)d_in[1];
    const float* b_l1 = (const float*)d_in[2];
    const float* W_l2 = (const float*)d_in[3];
    const float* b_l2 = (const float*)d_in[4];
    const float* W_c1 = (const float*)d_in[5];
    const float* b_c1 = (const float*)d_in[6];
    const float* W_c2 = (const float*)d_in[7];
    const float* b_c2 = (const float*)d_in[8];
    const float* W_c3 = (const float*)d_in[9];
    const float* b_c3 = (const float*)d_in[10];

    float* out = (float*)d_out;
    float* xout = nullptr;
    float* fineout = out;
    if (out_size >= 24576 + 393216) {   // x (8*1024*3) then fine (8*16384*3)
        xout = out;
        fineout = out + 24576;
    }

    float *h1p, *xp, *fcp;
    cudaGetSymbolAddress((void**)&h1p, g_h1);
    cudaGetSymbolAddress((void**)&xp, g_x);
    cudaGetSymbolAddress((void**)&fcp, g_fcon);
    cudaFuncSetAttribute(gemm_kernel,
                         cudaFuncAttributeMaxDynamicSharedMemorySize, G_SMEM);

    // independent weight transpose first
    wprep_kernel<<<dim3(16, 16), dim3(32, 8)>>>(W_c2);

    // coarse branch: fused lin1+fcon (24 blocks), then lin2 (48 blocks)
    linA_kernel<<<24, 256>>>(fea, W_l1, b_l1, W_c1 + 5 * 512, b_c1, h1p, fcp);
    lin2_kernel<<<48, 256>>>(h1p, W_l2, b_l2, xp, xout);

    // H production (fp16) + fine_out base; 16 points per block
    p1_kernel<<<512, 256>>>(W_c1, b_c3, fineout);

    // conv2 fp16 HMMA GEMM; epilogue atomically adds conv3 partials
    gemm_kernel<<<dim3(4, 1024), 256, G_SMEM>>>(b_c2, W_c3, fineout);
}